// round 3
// baseline (speedup 1.0000x reference)
#include <cuda_runtime.h>

// ---------------- problem constants ----------------
#define N_NODES 10000
#define N_EDGES 100000
#define EE      110000          // edges + self loops
#define G_IN    2000
#define H       20
#define C       128
#define HC      2560            // H * C
#define NEG_SLOPE 0.2f

// ---------------- scratch (device globals; no allocations) ----------------
__device__ float g_h[(size_t)N_NODES * HC];      // transformed features (layer 1 then layer 2)
__device__ float g_o[(size_t)N_NODES * HC];      // layer-1 aggregated output (layer-2 GEMM input)
__device__ float g_asrc[N_NODES * H];
__device__ float g_adst[N_NODES * H];
__device__ float g_alpha[(size_t)EE * H];
__device__ int   g_rowptr[N_NODES + 1];
__device__ int   g_deg[N_NODES];
__device__ int   g_fill[N_NODES];
__device__ int   g_csrc[EE];
__device__ int   g_is64;
__device__ int   g_esrc[N_EDGES];
__device__ int   g_edst[N_EDGES];

// ---------------- edge dtype detection + normalization ----------------
// If edge_index is int64 (little-endian), the odd 32-bit words are high words
// of values < 10^4 -> all zero. If int32, odd words are random node ids.
__global__ void k_detect(const int* __restrict__ ei32) {
    __shared__ int any;
    if (threadIdx.x == 0) any = 0;
    __syncthreads();
    if (ei32[2 * threadIdx.x + 1] != 0) atomicOr(&any, 1);
    __syncthreads();
    if (threadIdx.x == 0) g_is64 = (any == 0) ? 1 : 0;
}

__global__ void k_norm(const int* __restrict__ ei32) {
    int e = blockIdx.x * blockDim.x + threadIdx.x;
    if (e >= N_EDGES) return;
    if (g_is64) {   // int64: low word holds the value
        g_esrc[e] = ei32[2 * e];
        g_edst[e] = ei32[2 * N_EDGES + 2 * e];
    } else {        // int32
        g_esrc[e] = ei32[e];
        g_edst[e] = ei32[N_EDGES + e];
    }
}

// ---------------- CSR build ----------------
__global__ void k_zero_deg() {
    int i = blockIdx.x * blockDim.x + threadIdx.x;
    if (i < N_NODES) g_deg[i] = 0;
}

__global__ void k_count() {
    int e = blockIdx.x * blockDim.x + threadIdx.x;
    if (e >= EE) return;
    int dst = (e < N_EDGES) ? g_edst[e] : (e - N_EDGES);
    atomicAdd(&g_deg[dst], 1);
}

__global__ void k_scan() {
    __shared__ int part[1024];
    int t = threadIdx.x;
    const int CH = (N_NODES + 1023) / 1024;   // 10
    int base = t * CH;
    int s = 0;
    for (int i = 0; i < CH; i++) {
        int idx = base + i;
        if (idx < N_NODES) s += g_deg[idx];
    }
    part[t] = s;
    __syncthreads();
    for (int o = 1; o < 1024; o <<= 1) {
        int v = (t >= o) ? part[t - o] : 0;
        __syncthreads();
        part[t] += v;
        __syncthreads();
    }
    int run = (t > 0) ? part[t - 1] : 0;
    for (int i = 0; i < CH; i++) {
        int idx = base + i;
        if (idx < N_NODES) {
            g_rowptr[idx] = run;
            g_fill[idx]   = run;
            run += g_deg[idx];
        }
    }
    if (t == 1023) g_rowptr[N_NODES] = part[1023];
}

__global__ void k_scatter() {
    int e = blockIdx.x * blockDim.x + threadIdx.x;
    if (e >= EE) return;
    int src, dst;
    if (e < N_EDGES) { src = g_esrc[e]; dst = g_edst[e]; }
    else             { src = e - N_EDGES; dst = src; }
    int pos = atomicAdd(&g_fill[dst], 1);
    g_csrc[pos] = src;
}

// ---------------- fp32 SGEMM into g_h: g_h[M,Nc] = A[M,K] @ B[K,Nc] ----------------
// LAYER2=false: A = external x pointer. LAYER2=true: A = g_o (device symbol).
// Requires Nc % 128 == 0 and K % 16 == 0 (true for both layers). M guarded.
#define BM 128
#define BN 128
#define BK 16

template <bool LAYER2>
__global__ __launch_bounds__(256)
void k_sgemm(int M, int Nc, int K,
             const float* __restrict__ Aext,
             const float* __restrict__ B)
{
    const float* __restrict__ A = LAYER2 ? (const float*)g_o : Aext;
    float* __restrict__ Cmat = g_h;

    __shared__ float As[BK][BM + 4];   // transposed A tile, padded
    __shared__ float Bs[BK][BN];

    int tid  = threadIdx.x;
    int row0 = blockIdx.y * BM;
    int col0 = blockIdx.x * BN;
    int tr   = tid >> 4;   // 0..15
    int tc   = tid & 15;   // 0..15

    float acc[8][8];
    #pragma unroll
    for (int i = 0; i < 8; i++)
        #pragma unroll
        for (int j = 0; j < 8; j++) acc[i][j] = 0.f;

    for (int kt = 0; kt < K; kt += BK) {
        // load A tile (BM x BK), transpose into As
        #pragma unroll
        for (int i = 0; i < 8; i++) {
            int idx = i * 256 + tid;
            int r = idx >> 4;
            int c = idx & 15;
            int gr = row0 + r;
            As[c][r] = (gr < M) ? A[(size_t)gr * K + kt + c] : 0.f;
        }
        // load B tile (BK x BN) with float4
        #pragma unroll
        for (int i = 0; i < 2; i++) {
            int idx = i * 256 + tid;
            int r  = idx >> 5;    // 0..15
            int c4 = idx & 31;    // 0..31
            *(float4*)&Bs[r][c4 * 4] =
                *(const float4*)&B[(size_t)(kt + r) * Nc + col0 + c4 * 4];
        }
        __syncthreads();

        #pragma unroll
        for (int k = 0; k < BK; k++) {
            float a[8], b[8];
            *(float4*)&a[0] = *(float4*)&As[k][tr * 8];
            *(float4*)&a[4] = *(float4*)&As[k][tr * 8 + 4];
            *(float4*)&b[0] = *(float4*)&Bs[k][tc * 8];
            *(float4*)&b[4] = *(float4*)&Bs[k][tc * 8 + 4];
            #pragma unroll
            for (int i = 0; i < 8; i++)
                #pragma unroll
                for (int j = 0; j < 8; j++)
                    acc[i][j] += a[i] * b[j];
        }
        __syncthreads();
    }

    #pragma unroll
    for (int i = 0; i < 8; i++) {
        int gr = row0 + tr * 8 + i;
        if (gr >= M) continue;
        float* cp = Cmat + (size_t)gr * Nc + col0 + tc * 8;
        *(float4*)&cp[0] = make_float4(acc[i][0], acc[i][1], acc[i][2], acc[i][3]);
        *(float4*)&cp[4] = make_float4(acc[i][4], acc[i][5], acc[i][6], acc[i][7]);
    }
}

// ---------------- attention scores: a_src/a_dst[n,h] = <g_h[n,h,:], att[h,:]> ----------------
__global__ void k_att(const float* __restrict__ wsrc,
                      const float* __restrict__ wdst)
{
    int gw   = (blockIdx.x * blockDim.x + threadIdx.x) >> 5;
    int lane = threadIdx.x & 31;
    if (gw >= N_NODES * H) return;
    int n  = gw / H;
    int hh = gw - n * H;
    const float* hp = g_h + (size_t)n * HC + hh * C;
    const float* ws = wsrc + hh * C;
    const float* wd = wdst + hh * C;
    float s1 = 0.f, s2 = 0.f;
    #pragma unroll
    for (int i = 0; i < 4; i++) {
        float v = hp[lane + i * 32];
        s1 += v * __ldg(&ws[lane + i * 32]);
        s2 += v * __ldg(&wd[lane + i * 32]);
    }
    #pragma unroll
    for (int o = 16; o; o >>= 1) {
        s1 += __shfl_down_sync(0xffffffffu, s1, o);
        s2 += __shfl_down_sync(0xffffffffu, s2, o);
    }
    if (lane == 0) { g_asrc[gw] = s1; g_adst[gw] = s2; }
}

// ---------------- per-(dst,head) softmax over incoming edges ----------------
__global__ void k_softmax() {
    int idx = blockIdx.x * blockDim.x + threadIdx.x;
    if (idx >= N_NODES * H) return;
    int dst = idx / H;
    int hh  = idx - dst * H;
    float ad = g_adst[dst * H + hh];
    int p0 = g_rowptr[dst], p1 = g_rowptr[dst + 1];
    float m = -1e30f;
    for (int p = p0; p < p1; p++) {
        int s = g_csrc[p];
        float ev = g_asrc[s * H + hh] + ad;
        ev = (ev > 0.f) ? ev : NEG_SLOPE * ev;
        g_alpha[(size_t)p * H + hh] = ev;
        m = fmaxf(m, ev);
    }
    float sum = 0.f;
    for (int p = p0; p < p1; p++) {
        float ex = __expf(g_alpha[(size_t)p * H + hh] - m);
        g_alpha[(size_t)p * H + hh] = ex;
        sum += ex;
    }
    float inv = 1.f / sum;
    for (int p = p0; p < p1; p++) g_alpha[(size_t)p * H + hh] *= inv;
}

// ---------------- layer-1 aggregation: g_o[dst,:] = relu(sum alpha*g_h[src,:] + b1) ----------------
__global__ __launch_bounds__(256)
void k_agg1(const float* __restrict__ b1)
{
    __shared__ float sal[H];
    int dst = blockIdx.x;
    int t   = threadIdx.x;
    int p0 = g_rowptr[dst], p1 = g_rowptr[dst + 1];
    float acc[10];
    #pragma unroll
    for (int j = 0; j < 10; j++) acc[j] = 0.f;

    for (int p = p0; p < p1; p++) {
        if (t < H) sal[t] = g_alpha[(size_t)p * H + t];
        __syncthreads();
        const float* hs = g_h + (size_t)g_csrc[p] * HC;
        #pragma unroll
        for (int j = 0; j < 10; j++) {
            int c = t + j * 256;
            acc[j] += sal[c >> 7] * hs[c];
        }
        __syncthreads();
    }
    float* op = g_o + (size_t)dst * HC;
    #pragma unroll
    for (int j = 0; j < 10; j++) {
        int c = t + j * 256;
        float v = acc[j] + b1[c];
        op[c] = (v > 0.f) ? v : 0.f;
    }
}

// ---------------- layer-2 aggregation: out[dst,c] = relu(mean_h(sum alpha*g_h) + b2) ----------------
__global__ __launch_bounds__(128)
void k_agg2(const float* __restrict__ b2, float* __restrict__ out)
{
    __shared__ float sal[H];
    int dst = blockIdx.x;
    int t   = threadIdx.x;
    int p0 = g_rowptr[dst], p1 = g_rowptr[dst + 1];
    float acc = 0.f;
    for (int p = p0; p < p1; p++) {
        if (t < H) sal[t] = g_alpha[(size_t)p * H + t];
        __syncthreads();
        const float* hs = g_h + (size_t)g_csrc[p] * HC;
        #pragma unroll
        for (int hh = 0; hh < H; hh++) acc += sal[hh] * hs[hh * C + t];
        __syncthreads();
    }
    float v = acc * (1.f / (float)H) + b2[t];
    out[dst * C + t] = (v > 0.f) ? v : 0.f;
}

// ---------------- launch ----------------
extern "C" void kernel_launch(void* const* d_in, const int* in_sizes, int n_in,
                              void* d_out, int out_size)
{
    const float* x   = (const float*)d_in[0];
    const int*   ei  = (const int*)d_in[1];     // int32 OR int64 — detected on device
    const float* W1  = (const float*)d_in[2];
    const float* as1 = (const float*)d_in[3];
    const float* ad1 = (const float*)d_in[4];
    const float* b1  = (const float*)d_in[5];
    const float* W2  = (const float*)d_in[6];
    const float* as2 = (const float*)d_in[7];
    const float* ad2 = (const float*)d_in[8];
    const float* b2  = (const float*)d_in[9];
    float* out = (float*)d_out;

    // edge dtype detection + normalization
    k_detect<<<1, 256>>>(ei);
    k_norm  <<<(N_EDGES + 255) / 256, 256>>>(ei);

    // CSR build (by destination, self-loops appended)
    k_zero_deg<<<(N_NODES + 255) / 256, 256>>>();
    k_count  <<<(EE + 255) / 256, 256>>>();
    k_scan   <<<1, 1024>>>();
    k_scatter<<<(EE + 255) / 256, 256>>>();

    dim3 gg(HC / BN, (N_NODES + BM - 1) / BM);   // (20, 79)
    int att_blocks = (N_NODES * H * 32 + 255) / 256;
    int sm_blocks  = (N_NODES * H + 255) / 256;

    // ----- layer 1 -----
    k_sgemm<false><<<gg, 256>>>(N_NODES, HC, G_IN, x, W1);
    k_att<<<att_blocks, 256>>>(as1, ad1);
    k_softmax<<<sm_blocks, 256>>>();
    k_agg1<<<N_NODES, 256>>>(b1);

    // ----- layer 2 -----
    k_sgemm<true><<<gg, 256>>>(N_NODES, HC, HC, (const float*)0, W2);
    k_att<<<att_blocks, 256>>>(as2, ad2);
    k_softmax<<<sm_blocks, 256>>>();
    k_agg2<<<N_NODES, 128>>>(b2, out);
}

// round 5
// speedup vs baseline: 3.3270x; 3.3270x over previous
#include <cuda_runtime.h>
#include <cuda_bf16.h>
#include <cstdint>

// ---------------- problem constants ----------------
#define N_NODES 10000
#define M_PAD   10112            // 79 * 128
#define N_EDGES 100000
#define EE      110000           // edges + self loops
#define G_IN    2000
#define K1_PAD  2048
#define H       20
#define C       128
#define HC      2560             // H * C
#define NEG_SLOPE 0.2f

// ---------------- scratch (device globals; no allocations) ----------------
__device__ float g_h[(size_t)N_NODES * HC];
__device__ float g_o[(size_t)N_NODES * HC];
__device__ float g_asrc[N_NODES * H];
__device__ float g_adst[N_NODES * H];
__device__ float g_alpha[(size_t)EE * H];
__device__ int   g_rowptr[N_NODES + 1];
__device__ int   g_deg[N_NODES];
__device__ int   g_fill[N_NODES];
__device__ int   g_csrc[EE];
__device__ int   g_is64;
__device__ int   g_esrc[N_EDGES];
__device__ int   g_edst[N_EDGES];
// bf16 hi/lo splits: W^T [n][k] and activations A [m][k], K padded
__device__ __nv_bfloat16 g_wthi[(size_t)HC * HC];
__device__ __nv_bfloat16 g_wtlo[(size_t)HC * HC];
__device__ __nv_bfloat16 g_ahi[(size_t)M_PAD * HC];
__device__ __nv_bfloat16 g_alo[(size_t)M_PAD * HC];

// ---------------- helpers ----------------
__device__ __forceinline__ uint32_t smem_u32(const void* p) {
    uint32_t a;
    asm("{ .reg .u64 t; cvta.to.shared.u64 t, %1; cvt.u32.u64 %0, t; }" : "=r"(a) : "l"(p));
    return a;
}
// pack two floats -> bf16x2 (a -> low half, b -> high half)
#define CVTBF2(res, a, b) asm("cvt.rn.bf16x2.f32 %0, %1, %2;" : "=r"(res) : "f"(b), "f"(a))
#define SWZ(off) ((off) ^ (((off) >> 3) & 0x70))

__device__ __forceinline__ void cp16(uint32_t dst, const void* src) {
    asm volatile("cp.async.cg.shared.global [%0], [%1], 16;" :: "r"(dst), "l"(src) : "memory");
}
__device__ __forceinline__ void cp_commit() {
    asm volatile("cp.async.commit_group;" ::: "memory");
}
template <int X> __device__ __forceinline__ void cp_wait() {
    asm volatile("cp.async.wait_group %0;" :: "n"(X) : "memory");
}
#define LDSM4(r0, r1, r2, r3, addr) \
    asm volatile("ldmatrix.sync.aligned.m8n8.x4.shared.b16 {%0,%1,%2,%3}, [%4];" \
        : "=r"(r0), "=r"(r1), "=r"(r2), "=r"(r3) : "r"(addr))
#define MMA(c, a, b) \
    asm volatile("mma.sync.aligned.m16n8k16.row.col.f32.bf16.bf16.f32 " \
        "{%0,%1,%2,%3}, {%4,%5,%6,%7}, {%8,%9}, {%0,%1,%2,%3};" \
        : "+f"((c)[0]), "+f"((c)[1]), "+f"((c)[2]), "+f"((c)[3]) \
        : "r"((a)[0]), "r"((a)[1]), "r"((a)[2]), "r"((a)[3]), "r"((b)[0]), "r"((b)[1]))

// ---------------- edge dtype detection + normalization ----------------
__global__ void k_detect(const int* __restrict__ ei32) {
    __shared__ int any;
    if (threadIdx.x == 0) any = 0;
    __syncthreads();
    if (ei32[2 * threadIdx.x + 1] != 0) atomicOr(&any, 1);
    __syncthreads();
    if (threadIdx.x == 0) g_is64 = (any == 0) ? 1 : 0;
}
__global__ void k_norm(const int* __restrict__ ei32) {
    int e = blockIdx.x * blockDim.x + threadIdx.x;
    if (e >= N_EDGES) return;
    if (g_is64) { g_esrc[e] = ei32[2 * e]; g_edst[e] = ei32[2 * N_EDGES + 2 * e]; }
    else        { g_esrc[e] = ei32[e];     g_edst[e] = ei32[N_EDGES + e]; }
}

// ---------------- CSR build ----------------
__global__ void k_zero_deg() {
    int i = blockIdx.x * blockDim.x + threadIdx.x;
    if (i < N_NODES) g_deg[i] = 0;
}
__global__ void k_count() {
    int e = blockIdx.x * blockDim.x + threadIdx.x;
    if (e >= EE) return;
    int dst = (e < N_EDGES) ? g_edst[e] : (e - N_EDGES);
    atomicAdd(&g_deg[dst], 1);
}
__global__ void k_scan() {
    __shared__ int part[1024];
    int t = threadIdx.x;
    const int CH = (N_NODES + 1023) / 1024;
    int base = t * CH, s = 0;
    for (int i = 0; i < CH; i++) { int idx = base + i; if (idx < N_NODES) s += g_deg[idx]; }
    part[t] = s;
    __syncthreads();
    for (int o = 1; o < 1024; o <<= 1) {
        int v = (t >= o) ? part[t - o] : 0;
        __syncthreads(); part[t] += v; __syncthreads();
    }
    int run = (t > 0) ? part[t - 1] : 0;
    for (int i = 0; i < CH; i++) {
        int idx = base + i;
        if (idx < N_NODES) { g_rowptr[idx] = run; g_fill[idx] = run; run += g_deg[idx]; }
    }
    if (t == 1023) g_rowptr[N_NODES] = part[1023];
}
__global__ void k_scatter() {
    int e = blockIdx.x * blockDim.x + threadIdx.x;
    if (e >= EE) return;
    int src, dst;
    if (e < N_EDGES) { src = g_esrc[e]; dst = g_edst[e]; }
    else             { src = e - N_EDGES; dst = src; }
    int pos = atomicAdd(&g_fill[dst], 1);
    g_csrc[pos] = src;
}

// ---------------- activation split: g_ahi/g_alo[m][kpad] = split(A[m][k]) ----------------
template <bool LAYER2>
__global__ void k_asplit(const float* __restrict__ Aext, int K, int KPAD) {
    const float* __restrict__ A = LAYER2 ? (const float*)g_o : Aext;
    int idx = blockIdx.x * blockDim.x + threadIdx.x;
    int rowlen4 = KPAD >> 2;
    if (idx >= N_NODES * rowlen4) return;
    int row = idx / rowlen4;
    int c4  = (idx - row * rowlen4) << 2;
    float v[4];
    #pragma unroll
    for (int j = 0; j < 4; j++) v[j] = (c4 + j < K) ? A[(size_t)row * K + c4 + j] : 0.f;
    uint32_t h0, h1, l0, l1;
    CVTBF2(h0, v[0], v[1]);
    CVTBF2(h1, v[2], v[3]);
    float r0 = v[0] - __uint_as_float(h0 << 16);
    float r1 = v[1] - __uint_as_float(h0 & 0xFFFF0000u);
    float r2 = v[2] - __uint_as_float(h1 << 16);
    float r3 = v[3] - __uint_as_float(h1 & 0xFFFF0000u);
    CVTBF2(l0, r0, r1);
    CVTBF2(l1, r2, r3);
    size_t o = (size_t)row * KPAD + c4;
    *(uint2*)&g_ahi[o] = make_uint2(h0, h1);
    *(uint2*)&g_alo[o] = make_uint2(l0, l1);
}

// ---------------- W transpose + split: g_wt*[n][kpad] = split(W[k][n]) ----------------
__global__ void k_wsplit(const float* __restrict__ W, int K, int KPAD) {
    __shared__ float tile[32][33];
    int n0 = blockIdx.y * 32, k0 = blockIdx.x * 32;
    int tx = threadIdx.x, ty = threadIdx.y;     // (32, 8)
    #pragma unroll
    for (int s = 0; s < 32; s += 8) {
        int k = k0 + ty + s;
        tile[ty + s][tx] = (k < K) ? W[(size_t)k * HC + n0 + tx] : 0.f;
    }
    __syncthreads();
    #pragma unroll
    for (int s = 0; s < 32; s += 8) {
        int n = n0 + ty + s;
        int k = k0 + tx;
        float v = tile[tx][ty + s];
        __nv_bfloat16 hb = __float2bfloat16_rn(v);
        float rlo = v - __bfloat162float(hb);
        g_wthi[(size_t)n * KPAD + k] = hb;
        g_wtlo[(size_t)n * KPAD + k] = __float2bfloat16_rn(rlo);
    }
}

// ---------------- bf16-split HMMA GEMM: g_h[M][HC] = A @ W ----------------
// CTA tile 128x128, K staged 64, 3-stage cp.async pipeline, warp tile 64x32.
#define STG 65536
#define OFF_ALO 16384
#define OFF_BHI 32768
#define OFF_BLO 49152
#define GSMEM (3 * STG)

__global__ __launch_bounds__(256)
void k_hgemm(int kpad)
{
    extern __shared__ char smem[];
    uint32_t sb = smem_u32(smem);
    int tid  = threadIdx.x;
    int lane = tid & 31;
    int wid  = tid >> 5;
    int wr   = wid >> 2;            // 0..1  (64-row slabs)
    int wc   = wid & 3;             // 0..3  (32-col slabs)
    int row0 = blockIdx.y * 128;
    int col0 = blockIdx.x * 128;
    int nkb  = kpad >> 6;

    float acc[4][4][4];
    #pragma unroll
    for (int i = 0; i < 4; i++)
        #pragma unroll
        for (int j = 0; j < 4; j++)
            #pragma unroll
            for (int q = 0; q < 4; q++) acc[i][j][q] = 0.f;

    // ---- stage issue: 16 cp.async per thread ----
    auto issue = [&](int kb) {
        int kt = kb << 6;
        uint32_t st = sb + (kb % 3) * STG;
        #pragma unroll
        for (int i = 0; i < 4; i++) {
            int idx = i * 256 + tid;         // 0..1023
            int r = idx >> 3, c = idx & 7;
            uint32_t off = SWZ((uint32_t)(r * 128 + c * 16));
            size_t ga = (size_t)(row0 + r) * kpad + kt + c * 8;
            size_t gb = (size_t)(col0 + r) * kpad + kt + c * 8;
            cp16(st + off,           g_ahi  + ga);
            cp16(st + OFF_ALO + off, g_alo  + ga);
            cp16(st + OFF_BHI + off, g_wthi + gb);
            cp16(st + OFF_BLO + off, g_wtlo + gb);
        }
    };

    issue(0); cp_commit();
    if (nkb > 1) issue(1);
    cp_commit();

    for (int kb = 0; kb < nkb; kb++) {
        cp_wait<1>();
        __syncthreads();
        if (kb + 2 < nkb) issue(kb + 2);
        cp_commit();

        uint32_t tb = sb + (kb % 3) * STG;
        #pragma unroll
        for (int k16 = 0; k16 < 4; k16++) {
            uint32_t ah[4][4], al[4][4], bh[4][2], bl[4][2];
            // A fragments: 16x16 per mt via ldmatrix.x4
            int arow = wr * 64 + (lane & 15);
            uint32_t acol = (uint32_t)(k16 * 32 + (lane >> 4) * 16);
            #pragma unroll
            for (int mt = 0; mt < 4; mt++) {
                uint32_t off = SWZ((uint32_t)((arow + mt * 16) * 128) + acol);
                LDSM4(ah[mt][0], ah[mt][1], ah[mt][2], ah[mt][3], tb + off);
                LDSM4(al[mt][0], al[mt][1], al[mt][2], al[mt][3], tb + OFF_ALO + off);
            }
            // B fragments: two n8 tiles per ldmatrix.x4
            int mi = lane >> 3;
            int brow_base = wc * 32 + ((mi >> 1) << 3) + (lane & 7);
            uint32_t bcol = (uint32_t)(k16 * 32 + (mi & 1) * 16);
            #pragma unroll
            for (int nt2 = 0; nt2 < 2; nt2++) {
                uint32_t off = SWZ((uint32_t)((brow_base + nt2 * 16) * 128) + bcol);
                LDSM4(bh[nt2 * 2][0], bh[nt2 * 2][1], bh[nt2 * 2 + 1][0], bh[nt2 * 2 + 1][1],
                      tb + OFF_BHI + off);
                LDSM4(bl[nt2 * 2][0], bl[nt2 * 2][1], bl[nt2 * 2 + 1][0], bl[nt2 * 2 + 1][1],
                      tb + OFF_BLO + off);
            }
            // 3-term MMAs
            #pragma unroll
            for (int mt = 0; mt < 4; mt++)
                #pragma unroll
                for (int nt = 0; nt < 4; nt++) {
                    MMA(acc[mt][nt], ah[mt], bh[nt]);
                    MMA(acc[mt][nt], ah[mt], bl[nt]);
                    MMA(acc[mt][nt], al[mt], bh[nt]);
                }
        }
    }

    // ---- epilogue: write C ----
    #pragma unroll
    for (int mt = 0; mt < 4; mt++) {
        int gr = row0 + wr * 64 + mt * 16 + (lane >> 2);
        #pragma unroll
        for (int nt = 0; nt < 4; nt++) {
            int gc = col0 + wc * 32 + nt * 8 + (lane & 3) * 2;
            if (gr < N_NODES)
                *(float2*)&g_h[(size_t)gr * HC + gc] = make_float2(acc[mt][nt][0], acc[mt][nt][1]);
            if (gr + 8 < N_NODES)
                *(float2*)&g_h[(size_t)(gr + 8) * HC + gc] = make_float2(acc[mt][nt][2], acc[mt][nt][3]);
        }
    }
}

// ---------------- attention scores ----------------
__global__ void k_att(const float* __restrict__ wsrc,
                      const float* __restrict__ wdst)
{
    int gw   = (blockIdx.x * blockDim.x + threadIdx.x) >> 5;
    int lane = threadIdx.x & 31;
    if (gw >= N_NODES * H) return;
    int n  = gw / H;
    int hh = gw - n * H;
    const float* hp = g_h + (size_t)n * HC + hh * C;
    const float* ws = wsrc + hh * C;
    const float* wd = wdst + hh * C;
    float s1 = 0.f, s2 = 0.f;
    #pragma unroll
    for (int i = 0; i < 4; i++) {
        float v = hp[lane + i * 32];
        s1 += v * __ldg(&ws[lane + i * 32]);
        s2 += v * __ldg(&wd[lane + i * 32]);
    }
    #pragma unroll
    for (int o = 16; o; o >>= 1) {
        s1 += __shfl_down_sync(0xffffffffu, s1, o);
        s2 += __shfl_down_sync(0xffffffffu, s2, o);
    }
    if (lane == 0) { g_asrc[gw] = s1; g_adst[gw] = s2; }
}

// ---------------- per-(dst,head) softmax ----------------
__global__ void k_softmax() {
    int idx = blockIdx.x * blockDim.x + threadIdx.x;
    if (idx >= N_NODES * H) return;
    int dst = idx / H;
    int hh  = idx - dst * H;
    float ad = g_adst[dst * H + hh];
    int p0 = g_rowptr[dst], p1 = g_rowptr[dst + 1];
    float m = -1e30f;
    for (int p = p0; p < p1; p++) {
        int s = g_csrc[p];
        float ev = g_asrc[s * H + hh] + ad;
        ev = (ev > 0.f) ? ev : NEG_SLOPE * ev;
        g_alpha[(size_t)p * H + hh] = ev;
        m = fmaxf(m, ev);
    }
    float sum = 0.f;
    for (int p = p0; p < p1; p++) {
        float ex = __expf(g_alpha[(size_t)p * H + hh] - m);
        g_alpha[(size_t)p * H + hh] = ex;
        sum += ex;
    }
    float inv = 1.f / sum;
    for (int p = p0; p < p1; p++) g_alpha[(size_t)p * H + hh] *= inv;
}

// ---------------- layer-1 aggregation ----------------
__global__ __launch_bounds__(256)
void k_agg1(const float* __restrict__ b1)
{
    __shared__ float sal[H];
    int dst = blockIdx.x;
    int t   = threadIdx.x;
    int p0 = g_rowptr[dst], p1 = g_rowptr[dst + 1];
    float acc[10];
    #pragma unroll
    for (int j = 0; j < 10; j++) acc[j] = 0.f;

    for (int p = p0; p < p1; p++) {
        if (t < H) sal[t] = g_alpha[(size_t)p * H + t];
        __syncthreads();
        const float* hs = g_h + (size_t)g_csrc[p] * HC;
        #pragma unroll
        for (int j = 0; j < 10; j++) {
            int c = t + j * 256;
            acc[j] += sal[c >> 7] * hs[c];
        }
        __syncthreads();
    }
    float* op = g_o + (size_t)dst * HC;
    #pragma unroll
    for (int j = 0; j < 10; j++) {
        int c = t + j * 256;
        float v = acc[j] + b1[c];
        op[c] = (v > 0.f) ? v : 0.f;
    }
}

// ---------------- layer-2 aggregation ----------------
__global__ __launch_bounds__(128)
void k_agg2(const float* __restrict__ b2, float* __restrict__ out)
{
    __shared__ float sal[H];
    int dst = blockIdx.x;
    int t   = threadIdx.x;
    int p0 = g_rowptr[dst], p1 = g_rowptr[dst + 1];
    float acc = 0.f;
    for (int p = p0; p < p1; p++) {
        if (t < H) sal[t] = g_alpha[(size_t)p * H + t];
        __syncthreads();
        const float* hs = g_h + (size_t)g_csrc[p] * HC;
        #pragma unroll
        for (int hh = 0; hh < H; hh++) acc += sal[hh] * hs[hh * C + t];
        __syncthreads();
    }
    float v = acc * (1.f / (float)H) + b2[t];
    out[dst * C + t] = (v > 0.f) ? v : 0.f;
}

// ---------------- launch ----------------
extern "C" void kernel_launch(void* const* d_in, const int* in_sizes, int n_in,
                              void* d_out, int out_size)
{
    const float* x   = (const float*)d_in[0];
    const int*   ei  = (const int*)d_in[1];
    const float* W1  = (const float*)d_in[2];
    const float* as1 = (const float*)d_in[3];
    const float* ad1 = (const float*)d_in[4];
    const float* b1  = (const float*)d_in[5];
    const float* W2  = (const float*)d_in[6];
    const float* as2 = (const float*)d_in[7];
    const float* ad2 = (const float*)d_in[8];
    const float* b2  = (const float*)d_in[9];
    float* out = (float*)d_out;

    cudaFuncSetAttribute(k_hgemm, cudaFuncAttributeMaxDynamicSharedMemorySize, GSMEM);

    // edge dtype detection + normalization + CSR build
    k_detect<<<1, 256>>>(ei);
    k_norm  <<<(N_EDGES + 255) / 256, 256>>>(ei);
    k_zero_deg<<<(N_NODES + 255) / 256, 256>>>();
    k_count  <<<(EE + 255) / 256, 256>>>();
    k_scan   <<<1, 1024>>>();
    k_scatter<<<(EE + 255) / 256, 256>>>();

    dim3 gg(HC / 128, M_PAD / 128);                 // (20, 79)
    int att_blocks = (N_NODES * H * 32 + 255) / 256;
    int sm_blocks  = (N_NODES * H + 255) / 256;
    dim3 wsb(32, 8);

    // ----- layer 1 -----
    int a1blocks = (N_NODES * (K1_PAD / 4) + 255) / 256;
    k_asplit<false><<<a1blocks, 256>>>(x, G_IN, K1_PAD);
    k_wsplit<<<dim3(K1_PAD / 32, HC / 32), wsb>>>(W1, G_IN, K1_PAD);
    k_hgemm<<<gg, 256, GSMEM>>>(K1_PAD);
    k_att<<<att_blocks, 256>>>(as1, ad1);
    k_softmax<<<sm_blocks, 256>>>();
    k_agg1<<<N_NODES, 256>>>(b1);

    // ----- layer 2 -----
    int a2blocks = (N_NODES * (HC / 4) + 255) / 256;
    k_asplit<true><<<a2blocks, 256>>>((const float*)0, HC, HC);
    k_wsplit<<<dim3(HC / 32, HC / 32), wsb>>>(W2, HC, HC);
    k_hgemm<<<gg, 256, GSMEM>>>(HC);
    k_att<<<att_blocks, 256>>>(as2, ad2);
    k_softmax<<<sm_blocks, 256>>>();
    k_agg2<<<N_NODES, 128>>>(b2, out);
}

// round 6
// speedup vs baseline: 3.5537x; 1.0682x over previous
#include <cuda_runtime.h>
#include <cuda_bf16.h>
#include <cstdint>

// ---------------- problem constants ----------------
#define N_NODES 10000
#define M_PAD   10112            // 79 * 128
#define N_EDGES 100000
#define EE      110000           // edges + self loops
#define G_IN    2000
#define K1_PAD  2048
#define H       20
#define C       128
#define HC      2560             // H * C
#define NEG_SLOPE 0.2f

// ---------------- scratch (device globals; no allocations) ----------------
__device__ float g_h[(size_t)N_NODES * HC];
__device__ float g_o[(size_t)N_NODES * HC];
__device__ float g_asrc[N_NODES * H];
__device__ float g_adst[N_NODES * H];
__device__ float g_alpha[(size_t)EE * H];
__device__ int   g_rowptr[N_NODES + 1];
__device__ int   g_deg[N_NODES];
__device__ int   g_fill[N_NODES];
__device__ int   g_csrc[EE];
__device__ int   g_is64;
__device__ int   g_esrc[N_EDGES];
__device__ int   g_edst[N_EDGES];
// bf16 hi/lo splits: W^T [n][k] and activations A [m][k], K padded
__device__ __nv_bfloat16 g_wthi[(size_t)HC * HC];
__device__ __nv_bfloat16 g_wtlo[(size_t)HC * HC];
__device__ __nv_bfloat16 g_ahi[(size_t)M_PAD * HC];
__device__ __nv_bfloat16 g_alo[(size_t)M_PAD * HC];

// ---------------- helpers ----------------
__device__ __forceinline__ uint32_t smem_u32(const void* p) {
    uint32_t a;
    asm("{ .reg .u64 t; cvta.to.shared.u64 t, %1; cvt.u32.u64 %0, t; }" : "=r"(a) : "l"(p));
    return a;
}
#define CVTBF2(res, a, b) asm("cvt.rn.bf16x2.f32 %0, %1, %2;" : "=r"(res) : "f"(b), "f"(a))
#define SWZ(off) ((off) ^ (((off) >> 3) & 0x70))

__device__ __forceinline__ void cp16(uint32_t dst, const void* src) {
    asm volatile("cp.async.cg.shared.global [%0], [%1], 16;" :: "r"(dst), "l"(src) : "memory");
}
__device__ __forceinline__ void cp_commit() {
    asm volatile("cp.async.commit_group;" ::: "memory");
}
template <int X> __device__ __forceinline__ void cp_wait() {
    asm volatile("cp.async.wait_group %0;" :: "n"(X) : "memory");
}
#define LDSM4(r0, r1, r2, r3, addr) \
    asm volatile("ldmatrix.sync.aligned.m8n8.x4.shared.b16 {%0,%1,%2,%3}, [%4];" \
        : "=r"(r0), "=r"(r1), "=r"(r2), "=r"(r3) : "r"(addr))
#define MMA(c, a, b) \
    asm volatile("mma.sync.aligned.m16n8k16.row.col.f32.bf16.bf16.f32 " \
        "{%0,%1,%2,%3}, {%4,%5,%6,%7}, {%8,%9}, {%0,%1,%2,%3};" \
        : "+f"((c)[0]), "+f"((c)[1]), "+f"((c)[2]), "+f"((c)[3]) \
        : "r"((a)[0]), "r"((a)[1]), "r"((a)[2]), "r"((a)[3]), "r"((b)[0]), "r"((b)[1]))

// ---------------- edge dtype detection + normalization ----------------
__global__ void k_detect(const int* __restrict__ ei32) {
    __shared__ int any;
    if (threadIdx.x == 0) any = 0;
    __syncthreads();
    if (ei32[2 * threadIdx.x + 1] != 0) atomicOr(&any, 1);
    __syncthreads();
    if (threadIdx.x == 0) g_is64 = (any == 0) ? 1 : 0;
}
__global__ void k_norm(const int* __restrict__ ei32) {
    int e = blockIdx.x * blockDim.x + threadIdx.x;
    if (e >= N_EDGES) return;
    if (g_is64) { g_esrc[e] = ei32[2 * e]; g_edst[e] = ei32[2 * N_EDGES + 2 * e]; }
    else        { g_esrc[e] = ei32[e];     g_edst[e] = ei32[N_EDGES + e]; }
}

// ---------------- CSR build ----------------
__global__ void k_zero_deg() {
    int i = blockIdx.x * blockDim.x + threadIdx.x;
    if (i < N_NODES) g_deg[i] = 0;
}
__global__ void k_count() {
    int e = blockIdx.x * blockDim.x + threadIdx.x;
    if (e >= EE) return;
    int dst = (e < N_EDGES) ? g_edst[e] : (e - N_EDGES);
    atomicAdd(&g_deg[dst], 1);
}
__global__ void k_scan() {
    __shared__ int part[1024];
    int t = threadIdx.x;
    const int CH = (N_NODES + 1023) / 1024;
    int base = t * CH, s = 0;
    for (int i = 0; i < CH; i++) { int idx = base + i; if (idx < N_NODES) s += g_deg[idx]; }
    part[t] = s;
    __syncthreads();
    for (int o = 1; o < 1024; o <<= 1) {
        int v = (t >= o) ? part[t - o] : 0;
        __syncthreads(); part[t] += v; __syncthreads();
    }
    int run = (t > 0) ? part[t - 1] : 0;
    for (int i = 0; i < CH; i++) {
        int idx = base + i;
        if (idx < N_NODES) { g_rowptr[idx] = run; g_fill[idx] = run; run += g_deg[idx]; }
    }
    if (t == 1023) g_rowptr[N_NODES] = part[1023];
}
__global__ void k_scatter() {
    int e = blockIdx.x * blockDim.x + threadIdx.x;
    if (e >= EE) return;
    int src, dst;
    if (e < N_EDGES) { src = g_esrc[e]; dst = g_edst[e]; }
    else             { src = e - N_EDGES; dst = src; }
    int pos = atomicAdd(&g_fill[dst], 1);
    g_csrc[pos] = src;
}

// ---------------- activation split: g_ahi/g_alo[m][kpad] = split(A[m][k]) ----------------
template <bool LAYER2>
__global__ void k_asplit(const float* __restrict__ Aext, int K, int KPAD) {
    const float* __restrict__ A = LAYER2 ? (const float*)g_o : Aext;
    int idx = blockIdx.x * blockDim.x + threadIdx.x;
    int rowlen4 = KPAD >> 2;
    if (idx >= N_NODES * rowlen4) return;
    int row = idx / rowlen4;
    int c4  = (idx - row * rowlen4) << 2;
    float v[4];
    #pragma unroll
    for (int j = 0; j < 4; j++) v[j] = (c4 + j < K) ? A[(size_t)row * K + c4 + j] : 0.f;
    uint32_t h0, h1, l0, l1;
    CVTBF2(h0, v[0], v[1]);
    CVTBF2(h1, v[2], v[3]);
    float r0 = v[0] - __uint_as_float(h0 << 16);
    float r1 = v[1] - __uint_as_float(h0 & 0xFFFF0000u);
    float r2 = v[2] - __uint_as_float(h1 << 16);
    float r3 = v[3] - __uint_as_float(h1 & 0xFFFF0000u);
    CVTBF2(l0, r0, r1);
    CVTBF2(l1, r2, r3);
    size_t o = (size_t)row * KPAD + c4;
    *(uint2*)&g_ahi[o] = make_uint2(h0, h1);
    *(uint2*)&g_alo[o] = make_uint2(l0, l1);
}

// ---------------- W transpose + split: g_wt*[n][kpad] = split(W[k][n]) ----------------
__global__ void k_wsplit(const float* __restrict__ W, int K, int KPAD) {
    __shared__ float tile[32][33];
    int n0 = blockIdx.y * 32, k0 = blockIdx.x * 32;
    int tx = threadIdx.x, ty = threadIdx.y;     // (32, 8)
    #pragma unroll
    for (int s = 0; s < 32; s += 8) {
        int k = k0 + ty + s;
        tile[ty + s][tx] = (k < K) ? W[(size_t)k * HC + n0 + tx] : 0.f;
    }
    __syncthreads();
    #pragma unroll
    for (int s = 0; s < 32; s += 8) {
        int n = n0 + ty + s;
        int k = k0 + tx;
        float v = tile[tx][ty + s];
        __nv_bfloat16 hb = __float2bfloat16_rn(v);
        float rlo = v - __bfloat162float(hb);
        g_wthi[(size_t)n * KPAD + k] = hb;
        g_wtlo[(size_t)n * KPAD + k] = __float2bfloat16_rn(rlo);
    }
}

// ---------------- bf16-split HMMA GEMM: g_h[M][HC] = A @ W ----------------
// CTA tile 128x256, K staged 64, 2-stage cp.async pipeline, warp tile 64x64.
#define STG2    98304             // AHI 16K | ALO 16K | BHI 32K | BLO 32K
#define OFF_ALO 16384
#define OFF_BHI 32768
#define OFF_BLO 65536
#define GSMEM   (2 * STG2)        // 192 KB

__global__ __launch_bounds__(256, 1)
void k_hgemm(int kpad)
{
    extern __shared__ char smem[];
    uint32_t sb = smem_u32(smem);
    int tid  = threadIdx.x;
    int lane = tid & 31;
    int wid  = tid >> 5;
    int wr   = wid >> 2;            // 0..1  (64-row slabs)
    int wc   = wid & 3;             // 0..3  (64-col slabs)
    int row0 = blockIdx.y * 128;
    int col0 = blockIdx.x * 256;
    int nkb  = kpad >> 6;

    float acc[4][8][4];
    #pragma unroll
    for (int i = 0; i < 4; i++)
        #pragma unroll
        for (int j = 0; j < 8; j++)
            #pragma unroll
            for (int q = 0; q < 4; q++) acc[i][j][q] = 0.f;

    // ---- stage issue: 24 cp.async per thread ----
    auto issue = [&](int kb) {
        int kt = kb << 6;
        uint32_t st = sb + (kb & 1) * STG2;
        #pragma unroll
        for (int i = 0; i < 4; i++) {                 // A: 128 rows
            int idx = i * 256 + tid;
            int r = idx >> 3, c = idx & 7;
            uint32_t off = SWZ((uint32_t)(r * 128 + c * 16));
            size_t ga = (size_t)(row0 + r) * kpad + kt + c * 8;
            cp16(st + off,           g_ahi + ga);
            cp16(st + OFF_ALO + off, g_alo + ga);
        }
        #pragma unroll
        for (int i = 0; i < 8; i++) {                 // B: 256 rows
            int idx = i * 256 + tid;
            int r = idx >> 3, c = idx & 7;
            uint32_t off = SWZ((uint32_t)(r * 128 + c * 16));
            size_t gb = (size_t)(col0 + r) * kpad + kt + c * 8;
            cp16(st + OFF_BHI + off, g_wthi + gb);
            cp16(st + OFF_BLO + off, g_wtlo + gb);
        }
    };

    issue(0); cp_commit();

    for (int kb = 0; kb < nkb; kb++) {
        if (kb + 1 < nkb) issue(kb + 1);
        cp_commit();
        cp_wait<1>();
        __syncthreads();

        uint32_t tb = sb + (kb & 1) * STG2;
        #pragma unroll
        for (int k16 = 0; k16 < 4; k16++) {
            uint32_t ah[4][4], al[4][4];
            int arow = wr * 64 + (lane & 15);
            uint32_t acol = (uint32_t)(k16 * 32 + (lane >> 4) * 16);
            #pragma unroll
            for (int mt = 0; mt < 4; mt++) {
                uint32_t off = SWZ((uint32_t)((arow + mt * 16) * 128) + acol);
                LDSM4(ah[mt][0], ah[mt][1], ah[mt][2], ah[mt][3], tb + off);
                LDSM4(al[mt][0], al[mt][1], al[mt][2], al[mt][3], tb + OFF_ALO + off);
            }
            int mi = lane >> 3;
            int brow = wc * 64 + ((mi >> 1) << 3) + (lane & 7);
            uint32_t bcol = (uint32_t)(k16 * 32 + (mi & 1) * 16);
            #pragma unroll
            for (int half = 0; half < 2; half++) {
                uint32_t bh[4][2], bl[4][2];
                #pragma unroll
                for (int q = 0; q < 2; q++) {
                    int nt2 = half * 2 + q;
                    uint32_t off = SWZ((uint32_t)((brow + nt2 * 16) * 128) + bcol);
                    LDSM4(bh[q * 2][0], bh[q * 2][1], bh[q * 2 + 1][0], bh[q * 2 + 1][1],
                          tb + OFF_BHI + off);
                    LDSM4(bl[q * 2][0], bl[q * 2][1], bl[q * 2 + 1][0], bl[q * 2 + 1][1],
                          tb + OFF_BLO + off);
                }
                #pragma unroll
                for (int mt = 0; mt < 4; mt++)
                    #pragma unroll
                    for (int ntl = 0; ntl < 4; ntl++) {
                        int nt = half * 4 + ntl;
                        MMA(acc[mt][nt], ah[mt], bh[ntl]);
                        MMA(acc[mt][nt], ah[mt], bl[ntl]);
                        MMA(acc[mt][nt], al[mt], bh[ntl]);
                    }
            }
        }
        __syncthreads();
    }

    // ---- epilogue ----
    #pragma unroll
    for (int mt = 0; mt < 4; mt++) {
        int gr = row0 + wr * 64 + mt * 16 + (lane >> 2);
        #pragma unroll
        for (int nt = 0; nt < 8; nt++) {
            int gc = col0 + wc * 64 + nt * 8 + (lane & 3) * 2;
            if (gr < N_NODES)
                *(float2*)&g_h[(size_t)gr * HC + gc] = make_float2(acc[mt][nt][0], acc[mt][nt][1]);
            if (gr + 8 < N_NODES)
                *(float2*)&g_h[(size_t)(gr + 8) * HC + gc] = make_float2(acc[mt][nt][2], acc[mt][nt][3]);
        }
    }
}

// ---------------- attention scores ----------------
__global__ void k_att(const float* __restrict__ wsrc,
                      const float* __restrict__ wdst)
{
    int gw   = (blockIdx.x * blockDim.x + threadIdx.x) >> 5;
    int lane = threadIdx.x & 31;
    if (gw >= N_NODES * H) return;
    int n  = gw / H;
    int hh = gw - n * H;
    const float* hp = g_h + (size_t)n * HC + hh * C;
    const float* ws = wsrc + hh * C;
    const float* wd = wdst + hh * C;
    float s1 = 0.f, s2 = 0.f;
    #pragma unroll
    for (int i = 0; i < 4; i++) {
        float v = hp[lane + i * 32];
        s1 += v * __ldg(&ws[lane + i * 32]);
        s2 += v * __ldg(&wd[lane + i * 32]);
    }
    #pragma unroll
    for (int o = 16; o; o >>= 1) {
        s1 += __shfl_down_sync(0xffffffffu, s1, o);
        s2 += __shfl_down_sync(0xffffffffu, s2, o);
    }
    if (lane == 0) { g_asrc[gw] = s1; g_adst[gw] = s2; }
}

// ---------------- per-(dst,head) softmax ----------------
__global__ void k_softmax() {
    int idx = blockIdx.x * blockDim.x + threadIdx.x;
    if (idx >= N_NODES * H) return;
    int dst = idx / H;
    int hh  = idx - dst * H;
    float ad = g_adst[dst * H + hh];
    int p0 = g_rowptr[dst], p1 = g_rowptr[dst + 1];
    float m = -1e30f;
    for (int p = p0; p < p1; p++) {
        int s = g_csrc[p];
        float ev = g_asrc[s * H + hh] + ad;
        ev = (ev > 0.f) ? ev : NEG_SLOPE * ev;
        g_alpha[(size_t)p * H + hh] = ev;
        m = fmaxf(m, ev);
    }
    float sum = 0.f;
    for (int p = p0; p < p1; p++) {
        float ex = __expf(g_alpha[(size_t)p * H + hh] - m);
        g_alpha[(size_t)p * H + hh] = ex;
        sum += ex;
    }
    float inv = 1.f / sum;
    for (int p = p0; p < p1; p++) g_alpha[(size_t)p * H + hh] *= inv;
}

// ---------------- layer-1 aggregation ----------------
__global__ __launch_bounds__(256)
void k_agg1(const float* __restrict__ b1)
{
    __shared__ float sal[H];
    int dst = blockIdx.x;
    int t   = threadIdx.x;
    int p0 = g_rowptr[dst], p1 = g_rowptr[dst + 1];
    float acc[10];
    #pragma unroll
    for (int j = 0; j < 10; j++) acc[j] = 0.f;

    for (int p = p0; p < p1; p++) {
        if (t < H) sal[t] = g_alpha[(size_t)p * H + t];
        __syncthreads();
        const float* hs = g_h + (size_t)g_csrc[p] * HC;
        #pragma unroll
        for (int j = 0; j < 10; j++) {
            int c = t + j * 256;
            acc[j] += sal[c >> 7] * hs[c];
        }
        __syncthreads();
    }
    float* op = g_o + (size_t)dst * HC;
    #pragma unroll
    for (int j = 0; j < 10; j++) {
        int c = t + j * 256;
        float v = acc[j] + b1[c];
        op[c] = (v > 0.f) ? v : 0.f;
    }
}

// ---------------- layer-2 aggregation ----------------
__global__ __launch_bounds__(128)
void k_agg2(const float* __restrict__ b2, float* __restrict__ out)
{
    __shared__ float sal[H];
    int dst = blockIdx.x;
    int t   = threadIdx.x;
    int p0 = g_rowptr[dst], p1 = g_rowptr[dst + 1];
    float acc = 0.f;
    for (int p = p0; p < p1; p++) {
        if (t < H) sal[t] = g_alpha[(size_t)p * H + t];
        __syncthreads();
        const float* hs = g_h + (size_t)g_csrc[p] * HC;
        #pragma unroll
        for (int hh = 0; hh < H; hh++) acc += sal[hh] * hs[hh * C + t];
        __syncthreads();
    }
    float v = acc * (1.f / (float)H) + b2[t];
    out[dst * C + t] = (v > 0.f) ? v : 0.f;
}

// ---------------- launch ----------------
extern "C" void kernel_launch(void* const* d_in, const int* in_sizes, int n_in,
                              void* d_out, int out_size)
{
    const float* x   = (const float*)d_in[0];
    const int*   ei  = (const int*)d_in[1];
    const float* W1  = (const float*)d_in[2];
    const float* as1 = (const float*)d_in[3];
    const float* ad1 = (const float*)d_in[4];
    const float* b1  = (const float*)d_in[5];
    const float* W2  = (const float*)d_in[6];
    const float* as2 = (const float*)d_in[7];
    const float* ad2 = (const float*)d_in[8];
    const float* b2  = (const float*)d_in[9];
    float* out = (float*)d_out;

    cudaFuncSetAttribute(k_hgemm, cudaFuncAttributeMaxDynamicSharedMemorySize, GSMEM);

    dim3 gg(HC / 256, M_PAD / 128);                 // (10, 79)
    int att_blocks = (N_NODES * H * 32 + 255) / 256;
    int sm_blocks  = (N_NODES * H + 255) / 256;
    dim3 wsb(32, 8);

    // ----- layer 1 GEMM first (k_hgemm at launch #4 so ncu's fixed -s capture hits it) -----
    int a1blocks = (N_NODES * (K1_PAD / 4) + 255) / 256;
    k_asplit<false><<<a1blocks, 256>>>(x, G_IN, K1_PAD);            // 1
    k_wsplit<<<dim3(K1_PAD / 32, HC / 32), wsb>>>(W1, G_IN, K1_PAD);// 2
    k_detect<<<1, 256>>>(ei);                                       // 3
    k_hgemm<<<gg, 256, GSMEM>>>(K1_PAD);                            // 4
    // edge normalization + CSR build (independent of GEMM)
    k_norm  <<<(N_EDGES + 255) / 256, 256>>>(ei);                   // 5
    k_zero_deg<<<(N_NODES + 255) / 256, 256>>>();                   // 6
    k_count  <<<(EE + 255) / 256, 256>>>();                         // 7
    k_scan   <<<1, 1024>>>();                                       // 8
    k_scatter<<<(EE + 255) / 256, 256>>>();                         // 9
    // layer-1 edge phase
    k_att<<<att_blocks, 256>>>(as1, ad1);
    k_softmax<<<sm_blocks, 256>>>();
    k_agg1<<<N_NODES, 256>>>(b1);

    // ----- layer 2 -----
    int a2blocks = (N_NODES * (HC / 4) + 255) / 256;
    k_asplit<true><<<a2blocks, 256>>>((const float*)0, HC, HC);
    k_wsplit<<<dim3(HC / 32, HC / 32), wsb>>>(W2, HC, HC);
    k_hgemm<<<gg, 256, GSMEM>>>(HC);
    k_att<<<att_blocks, 256>>>(as2, ad2);
    k_softmax<<<sm_blocks, 256>>>();
    k_agg2<<<N_NODES, 128>>>(b2, out);
}